// round 11
// baseline (speedup 1.0000x reference)
#include <cuda_runtime.h>
#include <cuda_fp16.h>
#include <cstdint>

#define CL 4096
#define IL 1024
#define NE 512
#define HS 64
#define BATCHN 8
#define CHUNK 16   // KV tiles per split-K chunk

// fp16 weights (pre-converted, tiny)
__device__ __half g_w[3][NE * HS];

// half scratch; q pre-scaled by 512^-0.5 * log2(e)
__device__ __half g_q[BATCHN * CL * HS];
__device__ __half g_k[BATCHN * CL * HS];
__device__ __half g_v[BATCHN * CL * HS];

// split-K partials: slot = ((b*64+qb)*4 + ci)
__device__ float g_part_o[2048 * 64 * 64];   // unnormalized O
__device__ float g_part_ml[2048 * 64 * 2];   // (m, l) per row
__device__ int   g_cnt[512];                 // arrival counters (self-resetting)

#define QSCALE 0.06375871654f  /* 512^-0.5 * log2(e) */

__device__ __forceinline__ uint32_t smem_u32(const void* p) {
    return (uint32_t)__cvta_generic_to_shared(p);
}
__device__ __forceinline__ uint32_t h2_as_u32(__half2 h) {
    return *reinterpret_cast<uint32_t*>(&h);
}
__device__ __forceinline__ uint32_t h2exp2u(uint32_t x) {
    uint32_t y;
    asm("ex2.approx.f16x2 %0,%1;" : "=r"(y) : "r"(x));
    return y;
}
__device__ __forceinline__ void ldsm4(uint32_t& r0, uint32_t& r1, uint32_t& r2,
                                      uint32_t& r3, uint32_t a) {
    asm volatile("ldmatrix.sync.aligned.m8n8.x4.shared.b16 {%0,%1,%2,%3},[%4];\n"
                 : "=r"(r0), "=r"(r1), "=r"(r2), "=r"(r3) : "r"(a));
}
__device__ __forceinline__ void ldsm4t(uint32_t& r0, uint32_t& r1, uint32_t& r2,
                                       uint32_t& r3, uint32_t a) {
    asm volatile("ldmatrix.sync.aligned.m8n8.x4.trans.shared.b16 {%0,%1,%2,%3},[%4];\n"
                 : "=r"(r0), "=r"(r1), "=r"(r2), "=r"(r3) : "r"(a));
}
__device__ __forceinline__ void mma16816(float c[4], const uint32_t a[4],
                                         uint32_t b0, uint32_t b1) {
    asm volatile(
        "mma.sync.aligned.m16n8k16.row.col.f32.f16.f16.f32 "
        "{%0,%1,%2,%3},{%4,%5,%6,%7},{%8,%9},{%0,%1,%2,%3};\n"
        : "+f"(c[0]), "+f"(c[1]), "+f"(c[2]), "+f"(c[3])
        : "r"(a[0]), "r"(a[1]), "r"(a[2]), "r"(a[3]), "r"(b0), "r"(b1));
}
__device__ __forceinline__ void cp16(uint32_t dst, const void* src) {
    asm volatile("cp.async.cg.shared.global [%0],[%1],16;\n" ::"r"(dst), "l"(src));
}
__device__ __forceinline__ float ex2f(float x) {
    float y;
    asm("ex2.approx.f32 %0, %1;" : "=f"(y) : "f"(x));
    return y;
}

#define KST 72   // fp16 smem row stride in halves
#define XFST 68  // fp32 smem row stride in floats

// ---------------------------------------------------------------------------
// Convert W only to fp16 (384 KB; ~2 us).
// ---------------------------------------------------------------------------
__global__ __launch_bounds__(256) void convw_kernel(const float* __restrict__ Wq,
                                                    const float* __restrict__ Wk,
                                                    const float* __restrict__ Wv) {
    const int NW1 = NE * HS / 4;   // float4 per matrix = 8192
    int i = blockIdx.x * blockDim.x + threadIdx.x;
    if (i >= 3 * NW1) return;
    int mi = i / NW1, r = i % NW1;
    const float* W = (mi == 0) ? Wq : ((mi == 1) ? Wk : Wv);
    float4 v = ((const float4*)W)[r];
    ((__half2*)g_w[mi])[r * 2]     = __floats2half2_rn(v.x, v.y);
    ((__half2*)g_w[mi])[r * 2 + 1] = __floats2half2_rn(v.z, v.w);
}

// ---------------------------------------------------------------------------
// Fused projection, 384 threads / 12 warps: warp = (matrix mi, m-stripe).
// cp.async double-buffers the *fp32* X tile; fp32->fp16 convert in smem.
// dyn smem: Xf32[2][64*68]f (34816B) + Xs[64*72]h (9216B) + W[2][3][64*72]h
//           (55296B)  = 99328 B.
// ---------------------------------------------------------------------------
extern __shared__ __align__(16) char sm_raw[];

__global__ __launch_bounds__(384) void proj_kernel(const float* __restrict__ x) {
    float* Xf[2] = {(float*)sm_raw, (float*)sm_raw + 64 * XFST};
    __half* Xs = (__half*)(sm_raw + 2 * 64 * XFST * 4);
    __half* Wbase = Xs + 64 * KST;
#define WBUF(buf, mi) (Wbase + ((buf) * 3 + (mi)) * 64 * KST)

    const int tid = threadIdx.x, lane = tid & 31, warp = tid >> 5;
    const int g = lane >> 2, tig = lane & 3;
    const int mm = lane >> 3, rr = lane & 7;
    const int mi = warp >> 2;        // matrix 0..2
    const int m0 = (warp & 3) * 16;  // m-stripe
    const int row0 = blockIdx.x * 64;
    const float* Xg = x + (size_t)row0 * NE;

    auto load_chunk = [&](int kc, int buf) {
        for (int c = tid; c < 1024; c += 384) {   // X fp32: 64 rows x 16 frags
            int r = c >> 4, f = c & 15;
            cp16(smem_u32(Xf[buf] + r * XFST + f * 4),
                 Xg + (size_t)r * NE + kc * 64 + f * 4);
        }
        for (int c = tid; c < 1536; c += 384) {   // W fp16: 3 x 64 rows x 8 frags
            int wm = c >> 9, cc = c & 511, r = cc >> 3, f = cc & 7;
            cp16(smem_u32(WBUF(buf, wm) + r * KST + f * 8),
                 g_w[wm] + (size_t)(kc * 64 + r) * HS + f * 8);
        }
        asm volatile("cp.async.commit_group;\n");
    };

    load_chunk(0, 0);
    load_chunk(1, 1);

    float acc[8][4] = {};

    for (int kc = 0; kc < NE / 64; kc++) {
        const int buf = kc & 1;
        if (kc + 1 < NE / 64) asm volatile("cp.async.wait_group 1;\n");
        else                  asm volatile("cp.async.wait_group 0;\n");
        __syncthreads();   // Xf[buf] ready; previous mma done with Xs

        // convert fp32 tile -> fp16 ldmatrix tile
        for (int c = tid; c < 2048; c += 384) {   // 64 rows x 32 float2
            int r = c >> 5, f = c & 31;
            float2 v = *(const float2*)(Xf[buf] + r * XFST + f * 2);
            *(__half2*)(Xs + r * KST + f * 2) = __floats2half2_rn(v.x, v.y);
        }
        __syncthreads();

        const uint32_t xb = smem_u32(Xs);
        const uint32_t wb = smem_u32(WBUF(buf, mi));
#pragma unroll
        for (int ks = 0; ks < 4; ks++) {
            uint32_t a[4];
            ldsm4(a[0], a[1], a[2], a[3],
                  xb + ((m0 + (mm & 1) * 8 + rr) * KST + ks * 16 + (mm >> 1) * 8) * 2);
#pragma unroll
            for (int j = 0; j < 4; j++) {
                uint32_t b0, b1, b2, b3;
                ldsm4t(b0, b1, b2, b3,
                       wb + ((ks * 16 + (mm & 1) * 8 + rr) * KST + j * 16 + (mm >> 1) * 8) * 2);
                mma16816(acc[2 * j], a, b0, b1);
                mma16816(acc[2 * j + 1], a, b2, b3);
            }
        }
        __syncthreads();   // mma done reading Xs & Wbuf before refill
        if (kc + 2 < NE / 64) load_chunk(kc + 2, buf);
    }

    __half* outp = (mi == 0) ? g_q : ((mi == 1) ? g_k : g_v);
    const float sc = (mi == 0) ? QSCALE : 1.0f;
    const int r0 = row0 + m0 + g, r1 = r0 + 8;
#pragma unroll
    for (int nt = 0; nt < 8; nt++) {
        int c = nt * 8 + 2 * tig;
        *(__half2*)(outp + (size_t)r0 * HS + c) =
            __floats2half2_rn(acc[nt][0] * sc, acc[nt][1] * sc);
        *(__half2*)(outp + (size_t)r1 * HS + c) =
            __floats2half2_rn(acc[nt][2] * sc, acc[nt][3] * sc);
    }
#undef WBUF
}

// ---------------------------------------------------------------------------
// Flash attention, split-K chunks; last-arriving chunk CTA combines inline.
// ---------------------------------------------------------------------------
__global__ __launch_bounds__(128, 4) void attn_kernel(float* __restrict__ out) {
    __half* sm_dyn = (__half*)sm_raw;
    const int qb = blockIdx.x;
    const int b = blockIdx.y;
    const int ci = blockIdx.z;

    const int kbEndFull = (qb < IL / 64) ? (IL / 64) : (qb + 1);
    const int c0 = ci * CHUNK;
    if (c0 >= kbEndFull) return;
    const int n = min(CHUNK, kbEndFull - c0);
    const int nc = (kbEndFull + CHUNK - 1) / CHUNK;

    const int tid = threadIdx.x, lane = tid & 31, warp = tid >> 5;
    const int g = lane >> 2, tig = lane & 3;
    const int mm = lane >> 3, rr = lane & 7;
    const int m0 = warp * 16;

    const __half* Q = g_q + (size_t)b * CL * HS + (size_t)qb * 64 * HS;
    const __half* K = g_k + (size_t)b * CL * HS + (size_t)c0 * 64 * HS;
    const __half* V = g_v + (size_t)b * CL * HS + (size_t)c0 * 64 * HS;

    __half* Ks[2] = {sm_dyn, sm_dyn + 2 * 64 * KST};
    __half* Vs[2] = {sm_dyn + 64 * KST, sm_dyn + 3 * 64 * KST};

    for (int i = tid; i < 512; i += 128) {
        int r = i >> 3, f = i & 7;
        *(uint4*)(Ks[0] + r * KST + f * 8) = *(const uint4*)(Q + r * HS + f * 8);
    }
    __syncthreads();
    uint32_t qa[4][4];
    {
        const uint32_t qbase = smem_u32(Ks[0]);
#pragma unroll
        for (int kc = 0; kc < 4; kc++)
            ldsm4(qa[kc][0], qa[kc][1], qa[kc][2], qa[kc][3],
                  qbase + ((m0 + (mm & 1) * 8 + rr) * KST + kc * 16 + (mm >> 1) * 8) * 2);
    }
    __syncthreads();

#pragma unroll
    for (int pf = 0; pf < 2; pf++) {
        const __half* gk = K + (size_t)pf * 64 * HS;
        const __half* gv = V + (size_t)pf * 64 * HS;
#pragma unroll
        for (int i = 0; i < 4; i++) {
            int c = tid + i * 128, r = c >> 3, f = c & 7;
            cp16(smem_u32(Ks[pf] + r * KST + f * 8), gk + r * HS + f * 8);
            cp16(smem_u32(Vs[pf] + r * KST + f * 8), gv + r * HS + f * 8);
        }
        asm volatile("cp.async.commit_group;\n");
    }

    float o[8][4] = {};
    float s[8][4] = {};
    float m[2] = {-1e30f, -1e30f};
    float l[2] = {0.f, 0.f};
    uint32_t pa[4][4];

    asm volatile("cp.async.wait_group 1;\n");
    __syncthreads();
    {
        const uint32_t kbase = smem_u32(Ks[0]);
#pragma unroll
        for (int kc = 0; kc < 4; kc++)
#pragma unroll
            for (int j = 0; j < 4; j++) {
                uint32_t b0, b1, b2, b3;
                ldsm4(b0, b1, b2, b3,
                      kbase + ((16 * j + (mm >> 1) * 8 + rr) * KST + kc * 16 + (mm & 1) * 8) * 2);
                mma16816(s[2 * j], qa[kc], b0, b1);
                mma16816(s[2 * j + 1], qa[kc], b2, b3);
            }
        if (c0 == qb && qb >= IL / 64) {
            const int r0 = m0 + g, r1 = r0 + 8;
#pragma unroll
            for (int nt = 0; nt < 8; nt++) {
                int c = nt * 8 + 2 * tig;
                if (c > r0)     s[nt][0] = -1e30f;
                if (c + 1 > r0) s[nt][1] = -1e30f;
                if (c > r1)     s[nt][2] = -1e30f;
                if (c + 1 > r1) s[nt][3] = -1e30f;
            }
        }
    }

    for (int i = 0; i < n; i++) {
        const int bi = i & 1;

#pragma unroll
        for (int h = 0; h < 2; h++) {
            float rm = -1e30f;
#pragma unroll
            for (int nt = 0; nt < 8; nt++)
                rm = fmaxf(rm, fmaxf(s[nt][2 * h], s[nt][2 * h + 1]));
            rm = fmaxf(rm, __shfl_xor_sync(0xffffffffu, rm, 1));
            rm = fmaxf(rm, __shfl_xor_sync(0xffffffffu, rm, 2));
            float mn = fmaxf(m[h], rm);
            float alpha = ex2f(m[h] - mn);
            m[h] = mn;
            float sum = 0.f;
#pragma unroll
            for (int nt = 0; nt < 8; nt++) {
                uint32_t p = h2exp2u(h2_as_u32(
                    __floats2half2_rn(s[nt][2 * h] - mn, s[nt][2 * h + 1] - mn)));
                pa[nt >> 1][(nt & 1) * 2 + h] = p;
                float2 f = __half22float2(*reinterpret_cast<__half2*>(&p));
                sum += f.x + f.y;
                o[nt][2 * h] *= alpha;
                o[nt][2 * h + 1] *= alpha;
            }
            sum += __shfl_xor_sync(0xffffffffu, sum, 1);
            sum += __shfl_xor_sync(0xffffffffu, sum, 2);
            l[h] = l[h] * alpha + sum;
        }

        if (i + 1 < n) {
            asm volatile("cp.async.wait_group 0;\n");
            __syncthreads();

#pragma unroll
            for (int nt = 0; nt < 8; nt++)
#pragma unroll
                for (int e = 0; e < 4; e++) s[nt][e] = 0.f;

            const uint32_t vbase = smem_u32(Vs[bi]);
            const uint32_t kbase = smem_u32(Ks[bi ^ 1]);
#pragma unroll
            for (int kc = 0; kc < 4; kc++)
#pragma unroll
                for (int j = 0; j < 4; j++) {
                    uint32_t v0, v1, v2, v3, k0, k1, k2, k3;
                    ldsm4t(v0, v1, v2, v3,
                           vbase + ((kc * 16 + (mm & 1) * 8 + rr) * KST + 16 * j + (mm >> 1) * 8) * 2);
                    ldsm4(k0, k1, k2, k3,
                          kbase + ((16 * j + (mm >> 1) * 8 + rr) * KST + kc * 16 + (mm & 1) * 8) * 2);
                    mma16816(o[2 * j], pa[kc], v0, v1);
                    mma16816(o[2 * j + 1], pa[kc], v2, v3);
                    mma16816(s[2 * j], qa[kc], k0, k1);
                    mma16816(s[2 * j + 1], qa[kc], k2, k3);
                }

            if (c0 + i + 1 == qb && qb >= IL / 64) {
                const int r0 = m0 + g, r1 = r0 + 8;
#pragma unroll
                for (int nt = 0; nt < 8; nt++) {
                    int c = nt * 8 + 2 * tig;
                    if (c > r0)     s[nt][0] = -1e30f;
                    if (c + 1 > r0) s[nt][1] = -1e30f;
                    if (c > r1)     s[nt][2] = -1e30f;
                    if (c + 1 > r1) s[nt][3] = -1e30f;
                }
            }
            __syncthreads();

            if (i + 2 < n) {
                const __half* gk = K + (size_t)(i + 2) * 64 * HS;
                const __half* gv = V + (size_t)(i + 2) * 64 * HS;
#pragma unroll
                for (int ii = 0; ii < 4; ii++) {
                    int c = tid + ii * 128, r = c >> 3, f = c & 7;
                    cp16(smem_u32(Ks[bi] + r * KST + f * 8), gk + r * HS + f * 8);
                    cp16(smem_u32(Vs[bi] + r * KST + f * 8), gv + r * HS + f * 8);
                }
                asm volatile("cp.async.commit_group;\n");
            }
        } else {
            const uint32_t vbase = smem_u32(Vs[bi]);
#pragma unroll
            for (int kc = 0; kc < 4; kc++)
#pragma unroll
                for (int j = 0; j < 4; j++) {
                    uint32_t v0, v1, v2, v3;
                    ldsm4t(v0, v1, v2, v3,
                           vbase + ((kc * 16 + (mm & 1) * 8 + rr) * KST + 16 * j + (mm >> 1) * 8) * 2);
                    mma16816(o[2 * j], pa[kc], v0, v1);
                    mma16816(o[2 * j + 1], pa[kc], v2, v3);
                }
        }
    }

    // ======================= epilogue =======================
    float* O = out + ((size_t)b * CL + qb * 64) * HS;
    const int r0 = m0 + g, r1 = r0 + 8;

    if (nc == 1) {
        const float inv0 = 1.0f / l[0], inv1 = 1.0f / l[1];
#pragma unroll
        for (int nt = 0; nt < 8; nt++) {
            int c = nt * 8 + 2 * tig;
            O[(size_t)r0 * HS + c]     = o[nt][0] * inv0;
            O[(size_t)r0 * HS + c + 1] = o[nt][1] * inv0;
            O[(size_t)r1 * HS + c]     = o[nt][2] * inv1;
            O[(size_t)r1 * HS + c + 1] = o[nt][3] * inv1;
        }
        return;
    }

    const int blkid = b * 64 + qb;
    const int slot0 = blkid * 4;
    {
        float* PO = g_part_o + (size_t)(slot0 + ci) * 4096;
#pragma unroll
        for (int nt = 0; nt < 8; nt++) {
            int c = nt * 8 + 2 * tig;
            PO[r0 * 64 + c]     = o[nt][0];
            PO[r0 * 64 + c + 1] = o[nt][1];
            PO[r1 * 64 + c]     = o[nt][2];
            PO[r1 * 64 + c + 1] = o[nt][3];
        }
        if (tig == 0) {
            float* ML = g_part_ml + (size_t)(slot0 + ci) * 128;
            ML[r0 * 2]     = m[0];
            ML[r0 * 2 + 1] = l[0];
            ML[r1 * 2]     = m[1];
            ML[r1 * 2 + 1] = l[1];
        }
    }
    __threadfence();

    __shared__ int ticket_s;
    if (tid == 0) ticket_s = atomicAdd(&g_cnt[blkid], 1);
    __syncthreads();
    if (ticket_s != nc - 1) return;

    if (tid == 0) g_cnt[blkid] = 0;   // reset for next graph replay
    __threadfence();

    float mo[3][2], lo[3][2], wo[3][2];
    int cjs[3], noth = 0;
    float M0 = m[0], M1 = m[1];
    for (int cj = 0; cj < nc; cj++) {
        if (cj == ci) continue;
        float2 a0 = *(const float2*)&g_part_ml[(size_t)(slot0 + cj) * 128 + r0 * 2];
        float2 a1 = *(const float2*)&g_part_ml[(size_t)(slot0 + cj) * 128 + r1 * 2];
        mo[noth][0] = a0.x; lo[noth][0] = a0.y;
        mo[noth][1] = a1.x; lo[noth][1] = a1.y;
        cjs[noth] = cj;
        M0 = fmaxf(M0, a0.x);
        M1 = fmaxf(M1, a1.x);
        noth++;
    }
    const float w0 = ex2f(m[0] - M0), w1 = ex2f(m[1] - M1);
    float L0 = l[0] * w0, L1 = l[1] * w1;
    for (int t = 0; t < noth; t++) {
        wo[t][0] = ex2f(mo[t][0] - M0);
        wo[t][1] = ex2f(mo[t][1] - M1);
        L0 += lo[t][0] * wo[t][0];
        L1 += lo[t][1] * wo[t][1];
    }
    const float invL0 = 1.0f / L0, invL1 = 1.0f / L1;

#pragma unroll
    for (int nt = 0; nt < 8; nt++) {
        int c = nt * 8 + 2 * tig;
        float v0 = o[nt][0] * w0, v1 = o[nt][1] * w0;
        float v2 = o[nt][2] * w1, v3 = o[nt][3] * w1;
        for (int t = 0; t < noth; t++) {
            const float* PO = g_part_o + (size_t)(slot0 + cjs[t]) * 4096;
            float2 p0 = *(const float2*)&PO[r0 * 64 + c];
            float2 p1 = *(const float2*)&PO[r1 * 64 + c];
            v0 += p0.x * wo[t][0];
            v1 += p0.y * wo[t][0];
            v2 += p1.x * wo[t][1];
            v3 += p1.y * wo[t][1];
        }
        O[(size_t)r0 * HS + c]     = v0 * invL0;
        O[(size_t)r0 * HS + c + 1] = v1 * invL0;
        O[(size_t)r1 * HS + c]     = v2 * invL1;
        O[(size_t)r1 * HS + c + 1] = v3 * invL1;
    }
}

extern "C" void kernel_launch(void* const* d_in, const int* in_sizes, int n_in,
                              void* d_out, int out_size) {
    const float* x  = (const float*)d_in[0];
    const float* Wq = (const float*)d_in[1];
    const float* Wk = (const float*)d_in[2];
    const float* Wv = (const float*)d_in[3];
    float* out = (float*)d_out;

    convw_kernel<<<96, 256>>>(Wq, Wk, Wv);

    const int proj_smem = 2 * 64 * XFST * 4 + 64 * KST * 2 + 6 * 64 * KST * 2;  // 99328
    cudaFuncSetAttribute(proj_kernel, cudaFuncAttributeMaxDynamicSharedMemorySize,
                         proj_smem);
    proj_kernel<<<BATCHN * CL / 64, 384, proj_smem>>>(x);

    const int attn_smem = 4 * 64 * KST * (int)sizeof(__half);  // 36864
    dim3 gattn(CL / 64, BATCHN, 4);
    attn_kernel<<<gattn, 128, attn_smem>>>(out);
}

// round 12
// speedup vs baseline: 1.3441x; 1.3441x over previous
#include <cuda_runtime.h>
#include <cuda_fp16.h>
#include <cstdint>

#define CL 4096
#define IL 1024
#define NE 512
#define HS 64
#define BATCHN 8
#define CHUNK 16   // KV tiles per split-K chunk

// half scratch; q pre-scaled by 512^-0.5 * log2(e)
__device__ __half g_q[BATCHN * CL * HS];
__device__ __half g_k[BATCHN * CL * HS];
__device__ __half g_v[BATCHN * CL * HS];

// split-K partials: slot = ((b*64+qb)*4 + ci) — only causal blocks (qb>=16) use these
__device__ float g_part_o[2048 * 64 * 64];   // unnormalized O
__device__ float g_part_ml[2048 * 64 * 2];   // (m, l) per row

#define QSCALE 0.06375871654f  /* 512^-0.5 * log2(e) */

__device__ __forceinline__ uint32_t smem_u32(const void* p) {
    return (uint32_t)__cvta_generic_to_shared(p);
}
__device__ __forceinline__ uint32_t h2_as_u32(__half2 h) {
    return *reinterpret_cast<uint32_t*>(&h);
}
__device__ __forceinline__ uint32_t h2exp2u(uint32_t x) {
    uint32_t y;
    asm("ex2.approx.f16x2 %0,%1;" : "=r"(y) : "r"(x));
    return y;
}
__device__ __forceinline__ void ldsm4(uint32_t& r0, uint32_t& r1, uint32_t& r2,
                                      uint32_t& r3, uint32_t a) {
    asm volatile("ldmatrix.sync.aligned.m8n8.x4.shared.b16 {%0,%1,%2,%3},[%4];\n"
                 : "=r"(r0), "=r"(r1), "=r"(r2), "=r"(r3) : "r"(a));
}
__device__ __forceinline__ void ldsm4t(uint32_t& r0, uint32_t& r1, uint32_t& r2,
                                       uint32_t& r3, uint32_t a) {
    asm volatile("ldmatrix.sync.aligned.m8n8.x4.trans.shared.b16 {%0,%1,%2,%3},[%4];\n"
                 : "=r"(r0), "=r"(r1), "=r"(r2), "=r"(r3) : "r"(a));
}
__device__ __forceinline__ void mma16816(float c[4], const uint32_t a[4],
                                         uint32_t b0, uint32_t b1) {
    asm volatile(
        "mma.sync.aligned.m16n8k16.row.col.f32.f16.f16.f32 "
        "{%0,%1,%2,%3},{%4,%5,%6,%7},{%8,%9},{%0,%1,%2,%3};\n"
        : "+f"(c[0]), "+f"(c[1]), "+f"(c[2]), "+f"(c[3])
        : "r"(a[0]), "r"(a[1]), "r"(a[2]), "r"(a[3]), "r"(b0), "r"(b1));
}
__device__ __forceinline__ void cp16(uint32_t dst, const void* src) {
    asm volatile("cp.async.cg.shared.global [%0],[%1],16;\n" ::"r"(dst), "l"(src));
}
__device__ __forceinline__ float ex2f(float x) {
    float y;
    asm("ex2.approx.f32 %0, %1;" : "=f"(y) : "f"(x));
    return y;
}

#define KST 72  // smem row stride in halves (conflict-free ldmatrix)

// ---------------------------------------------------------------------------
// Fused projection: 384 threads / 12 warps = (matrix mi, m-stripe).
// X chunk register-double-buffered (prefetch during mma); W direct-load.
// ---------------------------------------------------------------------------
__global__ __launch_bounds__(384) void proj_kernel(const float* __restrict__ x,
                                                   const float* __restrict__ Wq,
                                                   const float* __restrict__ Wk,
                                                   const float* __restrict__ Wv) {
    __shared__ __align__(16) __half Xs[64 * KST];
    __shared__ __align__(16) __half Ws[3][64 * KST];

    const float* Wp[3] = {Wq, Wk, Wv};

    const int tid = threadIdx.x, lane = tid & 31, warp = tid >> 5;
    const int g = lane >> 2, tig = lane & 3;
    const int mm = lane >> 3, rr = lane & 7;
    const int mi = warp >> 2;        // matrix 0..2
    const int m0 = (warp & 3) * 16;  // m-stripe
    const int row0 = blockIdx.x * 64;
    const float4* X4 = (const float4*)x;

    // X chunk = 64 rows x 16 float4 = 1024 float4; 3 per thread (last partial)
    float4 xr[3];
#pragma unroll
    for (int j = 0; j < 3; j++) {
        int c = tid + j * 384;
        if (c < 1024) {
            int r = c >> 4, f = c & 15;
            xr[j] = X4[(size_t)(row0 + r) * (NE / 4) + f];   // kc = 0
        }
    }

    float acc[8][4] = {};

    for (int kc = 0; kc < NE / 64; kc++) {
        // ---- store X regs (convert) + load W chunk ----
#pragma unroll
        for (int j = 0; j < 3; j++) {
            int c = tid + j * 384;
            if (c < 1024) {
                int r = c >> 4, f = c & 15;
                *(__half2*)(Xs + r * KST + f * 4)     = __floats2half2_rn(xr[j].x, xr[j].y);
                *(__half2*)(Xs + r * KST + f * 4 + 2) = __floats2half2_rn(xr[j].z, xr[j].w);
            }
        }
#pragma unroll
        for (int j = 0; j < 8; j++) {   // W: 3 x 1024 float4 = 3072; 8/thread
            int c = tid + j * 384;
            int wm = c >> 10, cc = c & 1023, r = cc >> 4, f = cc & 15;
            float4 wv = ((const float4*)Wp[wm])[(size_t)(kc * 64 + r) * (HS / 4) + f];
            *(__half2*)(Ws[wm] + r * KST + f * 4)     = __floats2half2_rn(wv.x, wv.y);
            *(__half2*)(Ws[wm] + r * KST + f * 4 + 2) = __floats2half2_rn(wv.z, wv.w);
        }
        __syncthreads();

        // ---- prefetch next X chunk into regs (overlaps with mma) ----
        if (kc + 1 < NE / 64) {
#pragma unroll
            for (int j = 0; j < 3; j++) {
                int c = tid + j * 384;
                if (c < 1024) {
                    int r = c >> 4, f = c & 15;
                    xr[j] = X4[(size_t)(row0 + r) * (NE / 4) + (kc + 1) * 16 + f];
                }
            }
        }

        // ---- mma ----
        const uint32_t xb = smem_u32(Xs);
        const uint32_t wb = smem_u32(Ws[mi]);
#pragma unroll
        for (int ks = 0; ks < 4; ks++) {
            uint32_t a[4];
            ldsm4(a[0], a[1], a[2], a[3],
                  xb + ((m0 + (mm & 1) * 8 + rr) * KST + ks * 16 + (mm >> 1) * 8) * 2);
#pragma unroll
            for (int j = 0; j < 4; j++) {
                uint32_t b0, b1, b2, b3;
                ldsm4t(b0, b1, b2, b3,
                       wb + ((ks * 16 + (mm & 1) * 8 + rr) * KST + j * 16 + (mm >> 1) * 8) * 2);
                mma16816(acc[2 * j], a, b0, b1);
                mma16816(acc[2 * j + 1], a, b2, b3);
            }
        }
        __syncthreads();   // mma done before next iteration overwrites smem
    }

    __half* outp = (mi == 0) ? g_q : ((mi == 1) ? g_k : g_v);
    const float sc = (mi == 0) ? QSCALE : 1.0f;
    const int r0 = row0 + m0 + g, r1 = r0 + 8;
#pragma unroll
    for (int nt = 0; nt < 8; nt++) {
        int c = nt * 8 + 2 * tig;
        *(__half2*)(outp + (size_t)r0 * HS + c) =
            __floats2half2_rn(acc[nt][0] * sc, acc[nt][1] * sc);
        *(__half2*)(outp + (size_t)r1 * HS + c) =
            __floats2half2_rn(acc[nt][2] * sc, acc[nt][3] * sc);
    }
}

// ---------------------------------------------------------------------------
// Flash attention, split-K chunks of <=16 KV tiles.
// qb < 16 (nc==1): direct normalized output write.  Else: partials.
// ---------------------------------------------------------------------------
extern __shared__ __half sm_dyn[];

__global__ __launch_bounds__(128, 4) void attn_kernel(float* __restrict__ out) {
    const int qb = blockIdx.x;
    const int b = blockIdx.y;
    const int ci = blockIdx.z;

    const int kbEndFull = (qb < IL / 64) ? (IL / 64) : (qb + 1);
    const int c0 = ci * CHUNK;
    if (c0 >= kbEndFull) return;
    const int n = min(CHUNK, kbEndFull - c0);
    const int nc = (kbEndFull + CHUNK - 1) / CHUNK;

    const int tid = threadIdx.x, lane = tid & 31, warp = tid >> 5;
    const int g = lane >> 2, tig = lane & 3;
    const int mm = lane >> 3, rr = lane & 7;
    const int m0 = warp * 16;

    const __half* Q = g_q + (size_t)b * CL * HS + (size_t)qb * 64 * HS;
    const __half* K = g_k + (size_t)b * CL * HS + (size_t)c0 * 64 * HS;
    const __half* V = g_v + (size_t)b * CL * HS + (size_t)c0 * 64 * HS;

    __half* Ks[2] = {sm_dyn, sm_dyn + 2 * 64 * KST};
    __half* Vs[2] = {sm_dyn + 64 * KST, sm_dyn + 3 * 64 * KST};

    for (int i = tid; i < 512; i += 128) {
        int r = i >> 3, f = i & 7;
        *(uint4*)(Ks[0] + r * KST + f * 8) = *(const uint4*)(Q + r * HS + f * 8);
    }
    __syncthreads();
    uint32_t qa[4][4];
    {
        const uint32_t qbase = smem_u32(Ks[0]);
#pragma unroll
        for (int kc = 0; kc < 4; kc++)
            ldsm4(qa[kc][0], qa[kc][1], qa[kc][2], qa[kc][3],
                  qbase + ((m0 + (mm & 1) * 8 + rr) * KST + kc * 16 + (mm >> 1) * 8) * 2);
    }
    __syncthreads();

#pragma unroll
    for (int pf = 0; pf < 2; pf++) {
        const __half* gk = K + (size_t)pf * 64 * HS;
        const __half* gv = V + (size_t)pf * 64 * HS;
#pragma unroll
        for (int i = 0; i < 4; i++) {
            int c = tid + i * 128, r = c >> 3, f = c & 7;
            cp16(smem_u32(Ks[pf] + r * KST + f * 8), gk + r * HS + f * 8);
            cp16(smem_u32(Vs[pf] + r * KST + f * 8), gv + r * HS + f * 8);
        }
        asm volatile("cp.async.commit_group;\n");
    }

    float o[8][4] = {};
    float s[8][4] = {};
    float m[2] = {-1e30f, -1e30f};
    float l[2] = {0.f, 0.f};
    uint32_t pa[4][4];

    asm volatile("cp.async.wait_group 1;\n");
    __syncthreads();
    {
        const uint32_t kbase = smem_u32(Ks[0]);
#pragma unroll
        for (int kc = 0; kc < 4; kc++)
#pragma unroll
            for (int j = 0; j < 4; j++) {
                uint32_t b0, b1, b2, b3;
                ldsm4(b0, b1, b2, b3,
                      kbase + ((16 * j + (mm >> 1) * 8 + rr) * KST + kc * 16 + (mm & 1) * 8) * 2);
                mma16816(s[2 * j], qa[kc], b0, b1);
                mma16816(s[2 * j + 1], qa[kc], b2, b3);
            }
        if (c0 == qb && qb >= IL / 64) {
            const int r0 = m0 + g, r1 = r0 + 8;
#pragma unroll
            for (int nt = 0; nt < 8; nt++) {
                int c = nt * 8 + 2 * tig;
                if (c > r0)     s[nt][0] = -1e30f;
                if (c + 1 > r0) s[nt][1] = -1e30f;
                if (c > r1)     s[nt][2] = -1e30f;
                if (c + 1 > r1) s[nt][3] = -1e30f;
            }
        }
    }

    for (int i = 0; i < n; i++) {
        const int bi = i & 1;

#pragma unroll
        for (int h = 0; h < 2; h++) {
            float rm = -1e30f;
#pragma unroll
            for (int nt = 0; nt < 8; nt++)
                rm = fmaxf(rm, fmaxf(s[nt][2 * h], s[nt][2 * h + 1]));
            rm = fmaxf(rm, __shfl_xor_sync(0xffffffffu, rm, 1));
            rm = fmaxf(rm, __shfl_xor_sync(0xffffffffu, rm, 2));
            float mn = fmaxf(m[h], rm);
            float alpha = ex2f(m[h] - mn);
            m[h] = mn;
            float sum = 0.f;
#pragma unroll
            for (int nt = 0; nt < 8; nt++) {
                uint32_t p = h2exp2u(h2_as_u32(
                    __floats2half2_rn(s[nt][2 * h] - mn, s[nt][2 * h + 1] - mn)));
                pa[nt >> 1][(nt & 1) * 2 + h] = p;
                float2 f = __half22float2(*reinterpret_cast<__half2*>(&p));
                sum += f.x + f.y;
                o[nt][2 * h] *= alpha;
                o[nt][2 * h + 1] *= alpha;
            }
            sum += __shfl_xor_sync(0xffffffffu, sum, 1);
            sum += __shfl_xor_sync(0xffffffffu, sum, 2);
            l[h] = l[h] * alpha + sum;
        }

        if (i + 1 < n) {
            asm volatile("cp.async.wait_group 0;\n");
            __syncthreads();

#pragma unroll
            for (int nt = 0; nt < 8; nt++)
#pragma unroll
                for (int e = 0; e < 4; e++) s[nt][e] = 0.f;

            const uint32_t vbase = smem_u32(Vs[bi]);
            const uint32_t kbase = smem_u32(Ks[bi ^ 1]);
#pragma unroll
            for (int kc = 0; kc < 4; kc++)
#pragma unroll
                for (int j = 0; j < 4; j++) {
                    uint32_t v0, v1, v2, v3, k0, k1, k2, k3;
                    ldsm4t(v0, v1, v2, v3,
                           vbase + ((kc * 16 + (mm & 1) * 8 + rr) * KST + 16 * j + (mm >> 1) * 8) * 2);
                    ldsm4(k0, k1, k2, k3,
                          kbase + ((16 * j + (mm >> 1) * 8 + rr) * KST + kc * 16 + (mm & 1) * 8) * 2);
                    mma16816(o[2 * j], pa[kc], v0, v1);
                    mma16816(o[2 * j + 1], pa[kc], v2, v3);
                    mma16816(s[2 * j], qa[kc], k0, k1);
                    mma16816(s[2 * j + 1], qa[kc], k2, k3);
                }

            if (c0 + i + 1 == qb && qb >= IL / 64) {
                const int r0 = m0 + g, r1 = r0 + 8;
#pragma unroll
                for (int nt = 0; nt < 8; nt++) {
                    int c = nt * 8 + 2 * tig;
                    if (c > r0)     s[nt][0] = -1e30f;
                    if (c + 1 > r0) s[nt][1] = -1e30f;
                    if (c > r1)     s[nt][2] = -1e30f;
                    if (c + 1 > r1) s[nt][3] = -1e30f;
                }
            }
            __syncthreads();

            if (i + 2 < n) {
                const __half* gk = K + (size_t)(i + 2) * 64 * HS;
                const __half* gv = V + (size_t)(i + 2) * 64 * HS;
#pragma unroll
                for (int ii = 0; ii < 4; ii++) {
                    int c = tid + ii * 128, r = c >> 3, f = c & 7;
                    cp16(smem_u32(Ks[bi] + r * KST + f * 8), gk + r * HS + f * 8);
                    cp16(smem_u32(Vs[bi] + r * KST + f * 8), gv + r * HS + f * 8);
                }
                asm volatile("cp.async.commit_group;\n");
            }
        } else {
            const uint32_t vbase = smem_u32(Vs[bi]);
#pragma unroll
            for (int kc = 0; kc < 4; kc++)
#pragma unroll
                for (int j = 0; j < 4; j++) {
                    uint32_t v0, v1, v2, v3;
                    ldsm4t(v0, v1, v2, v3,
                           vbase + ((kc * 16 + (mm & 1) * 8 + rr) * KST + 16 * j + (mm >> 1) * 8) * 2);
                    mma16816(o[2 * j], pa[kc], v0, v1);
                    mma16816(o[2 * j + 1], pa[kc], v2, v3);
                }
        }
    }

    // ---- epilogue ----
    const int r0 = m0 + g, r1 = r0 + 8;
    if (nc == 1) {   // prefix blocks: final output directly
        float* O = out + ((size_t)b * CL + qb * 64) * HS;
        const float inv0 = 1.0f / l[0], inv1 = 1.0f / l[1];
#pragma unroll
        for (int nt = 0; nt < 8; nt++) {
            int c = nt * 8 + 2 * tig;
            O[(size_t)r0 * HS + c]     = o[nt][0] * inv0;
            O[(size_t)r0 * HS + c + 1] = o[nt][1] * inv0;
            O[(size_t)r1 * HS + c]     = o[nt][2] * inv1;
            O[(size_t)r1 * HS + c + 1] = o[nt][3] * inv1;
        }
        return;
    }

    const int slot = (b * 64 + qb) * 4 + ci;
    float* PO = g_part_o + (size_t)slot * 4096;
#pragma unroll
    for (int nt = 0; nt < 8; nt++) {
        int c = nt * 8 + 2 * tig;
        PO[r0 * 64 + c]     = o[nt][0];
        PO[r0 * 64 + c + 1] = o[nt][1];
        PO[r1 * 64 + c]     = o[nt][2];
        PO[r1 * 64 + c + 1] = o[nt][3];
    }
    if (tig == 0) {
        float* ML = g_part_ml + (size_t)slot * 128;
        ML[r0 * 2]     = m[0];
        ML[r0 * 2 + 1] = l[0];
        ML[r1 * 2]     = m[1];
        ML[r1 * 2 + 1] = l[1];
    }
}

// ---------------------------------------------------------------------------
// Combine split-K partials — causal blocks only (qb >= 16; nc in 2..4).
// ---------------------------------------------------------------------------
__global__ __launch_bounds__(256) void combine_kernel(float* __restrict__ out) {
    const int qb = 16 + blockIdx.x;            // 16..63
    const int b = blockIdx.y;
    const int nc = (qb + 16) / 16;             // ceil((qb+1)/16), qb>=16
    const int tid = threadIdx.x;
    const int slot0 = (b * 64 + qb) * 4;

    __shared__ float wsc[4][64];

    if (tid < 64) {
        float mv[4], lv[4];
        float M = -1e30f;
        for (int ci = 0; ci < nc; ci++) {
            mv[ci] = g_part_ml[(size_t)(slot0 + ci) * 128 + tid * 2];
            lv[ci] = g_part_ml[(size_t)(slot0 + ci) * 128 + tid * 2 + 1];
            M = fmaxf(M, mv[ci]);
        }
        float L = 0.f;
        for (int ci = 0; ci < nc; ci++) {
            float w = ex2f(mv[ci] - M);
            mv[ci] = w;
            L += lv[ci] * w;
        }
        float invL = 1.0f / L;
        for (int ci = 0; ci < nc; ci++) wsc[ci][tid] = mv[ci] * invL;
    }
    __syncthreads();

    const float4* P = (const float4*)(g_part_o + (size_t)slot0 * 4096);
    float4* O = (float4*)(out + ((size_t)b * CL + qb * 64) * HS);
#pragma unroll
    for (int k = 0; k < 4; k++) {
        int idx = tid + k * 256;   // 0..1023 float4 (64 rows x 16)
        int row = idx >> 4;
        float4 acc = {0.f, 0.f, 0.f, 0.f};
        for (int ci = 0; ci < nc; ci++) {
            float w = wsc[ci][row];
            float4 v = P[ci * 1024 + idx];
            acc.x += v.x * w;
            acc.y += v.y * w;
            acc.z += v.z * w;
            acc.w += v.w * w;
        }
        O[idx] = acc;
    }
}

extern "C" void kernel_launch(void* const* d_in, const int* in_sizes, int n_in,
                              void* d_out, int out_size) {
    const float* x  = (const float*)d_in[0];
    const float* Wq = (const float*)d_in[1];
    const float* Wk = (const float*)d_in[2];
    const float* Wv = (const float*)d_in[3];
    float* out = (float*)d_out;

    proj_kernel<<<BATCHN * CL / 64, 384>>>(x, Wq, Wk, Wv);

    const int attn_smem = 4 * 64 * KST * (int)sizeof(__half);  // 36864
    dim3 gattn(CL / 64, BATCHN, 4);
    attn_kernel<<<gattn, 128, attn_smem>>>(out);

    dim3 gcomb(48, BATCHN);
    combine_kernel<<<gcomb, 256>>>(out);
}

// round 13
// speedup vs baseline: 1.6043x; 1.1936x over previous
#include <cuda_runtime.h>
#include <cuda_fp16.h>
#include <cstdint>

#define CL 4096
#define IL 1024
#define NE 512
#define HS 64
#define BATCHN 8
#define CHUNK 16   // KV tiles per split-K chunk

// fp16 weights (pre-converted)
__device__ __half g_w[3][NE * HS];

// half scratch; q pre-scaled by 512^-0.5 * log2(e)
__device__ __half g_q[BATCHN * CL * HS];
__device__ __half g_k[BATCHN * CL * HS];
__device__ __half g_v[BATCHN * CL * HS];

// split-K partials: slot = ((b*64+qb)*4 + ci) — only causal blocks (qb>=16)
__device__ float g_part_o[2048 * 64 * 64];   // unnormalized O
__device__ float g_part_ml[2048 * 64 * 2];   // (m, l) per row

#define QSCALE 0.06375871654f  /* 512^-0.5 * log2(e) */

__device__ __forceinline__ uint32_t smem_u32(const void* p) {
    return (uint32_t)__cvta_generic_to_shared(p);
}
__device__ __forceinline__ uint32_t h2_as_u32(__half2 h) {
    return *reinterpret_cast<uint32_t*>(&h);
}
__device__ __forceinline__ uint32_t h2exp2u(uint32_t x) {
    uint32_t y;
    asm("ex2.approx.f16x2 %0,%1;" : "=r"(y) : "r"(x));
    return y;
}
__device__ __forceinline__ void ldsm4(uint32_t& r0, uint32_t& r1, uint32_t& r2,
                                      uint32_t& r3, uint32_t a) {
    asm volatile("ldmatrix.sync.aligned.m8n8.x4.shared.b16 {%0,%1,%2,%3},[%4];\n"
                 : "=r"(r0), "=r"(r1), "=r"(r2), "=r"(r3) : "r"(a));
}
__device__ __forceinline__ void ldsm4t(uint32_t& r0, uint32_t& r1, uint32_t& r2,
                                       uint32_t& r3, uint32_t a) {
    asm volatile("ldmatrix.sync.aligned.m8n8.x4.trans.shared.b16 {%0,%1,%2,%3},[%4];\n"
                 : "=r"(r0), "=r"(r1), "=r"(r2), "=r"(r3) : "r"(a));
}
__device__ __forceinline__ void mma16816(float c[4], const uint32_t a[4],
                                         uint32_t b0, uint32_t b1) {
    asm volatile(
        "mma.sync.aligned.m16n8k16.row.col.f32.f16.f16.f32 "
        "{%0,%1,%2,%3},{%4,%5,%6,%7},{%8,%9},{%0,%1,%2,%3};\n"
        : "+f"(c[0]), "+f"(c[1]), "+f"(c[2]), "+f"(c[3])
        : "r"(a[0]), "r"(a[1]), "r"(a[2]), "r"(a[3]), "r"(b0), "r"(b1));
}
__device__ __forceinline__ void cp16(uint32_t dst, const void* src) {
    asm volatile("cp.async.cg.shared.global [%0],[%1],16;\n" ::"r"(dst), "l"(src));
}
__device__ __forceinline__ float ex2f(float x) {
    float y;
    asm("ex2.approx.f32 %0, %1;" : "=f"(y) : "f"(x));
    return y;
}

#define KST 72  // smem row stride in halves (conflict-free ldmatrix)

// ---------------------------------------------------------------------------
// Convert W to fp16 (384 KB; one-off).
// ---------------------------------------------------------------------------
__global__ __launch_bounds__(256) void convw_kernel(const float* __restrict__ Wq,
                                                    const float* __restrict__ Wk,
                                                    const float* __restrict__ Wv) {
    const int NW1 = NE * HS / 4;   // float4 per matrix = 8192
    int i = blockIdx.x * blockDim.x + threadIdx.x;
    if (i >= 3 * NW1) return;
    int mi = i / NW1, r = i % NW1;
    const float* W = (mi == 0) ? Wq : ((mi == 1) ? Wk : Wv);
    float4 v = ((const float4*)W)[r];
    ((__half2*)g_w[mi])[r * 2]     = __floats2half2_rn(v.x, v.y);
    ((__half2*)g_w[mi])[r * 2 + 1] = __floats2half2_rn(v.z, v.w);
}

// ---------------------------------------------------------------------------
// Fused projection: 384 threads / 12 warps = (matrix mi, m-stripe).
// W fp16 via cp.async double-buffer (off critical path);
// X fp32 register-prefetched during mma, converted at store.
// dyn smem: Xs[64*72]h (9216 B) + W[2][3][64*72]h (55296 B) = 64512 B.
// ---------------------------------------------------------------------------
extern __shared__ __half sm_dyn[];

__global__ __launch_bounds__(384) void proj_kernel(const float* __restrict__ x) {
    __half* Xs = sm_dyn;
    __half* Wbase = sm_dyn + 64 * KST;
#define WBUF(buf, wm) (Wbase + ((buf) * 3 + (wm)) * 64 * KST)

    const int tid = threadIdx.x, lane = tid & 31, warp = tid >> 5;
    const int g = lane >> 2, tig = lane & 3;
    const int mm = lane >> 3, rr = lane & 7;
    const int mi = warp >> 2;        // matrix 0..2
    const int m0 = (warp & 3) * 16;  // m-stripe
    const int row0 = blockIdx.x * 64;
    const float4* X4 = (const float4*)x;

    // ---- cp.async W loader: chunk kc -> buffer buf (1536 cp16 / 384 thr) ----
    auto load_w = [&](int kc, int buf) {
#pragma unroll
        for (int j = 0; j < 4; j++) {
            int c = tid + j * 384;
            int wm = c >> 9, cc = c & 511, r = cc >> 3, f = cc & 7;
            cp16(smem_u32(WBUF(buf, wm) + r * KST + f * 8),
                 g_w[wm] + (size_t)(kc * 64 + r) * HS + f * 8);
        }
        asm volatile("cp.async.commit_group;\n");
    };

    load_w(0, 0);
    load_w(1, 1);

    // ---- prologue: X chunk 0 into regs (3 float4/thread, last partial) ----
    float4 xr[3];
#pragma unroll
    for (int j = 0; j < 3; j++) {
        int c = tid + j * 384;
        if (c < 1024) {
            int r = c >> 4, f = c & 15;
            xr[j] = X4[(size_t)(row0 + r) * (NE / 4) + f];
        }
    }

    float acc[8][4] = {};

    for (int kc = 0; kc < NE / 64; kc++) {
        const int buf = kc & 1;

        // ---- phase 1: store X(kc) regs -> Xs (convert) ----
#pragma unroll
        for (int j = 0; j < 3; j++) {
            int c = tid + j * 384;
            if (c < 1024) {
                int r = c >> 4, f = c & 15;
                *(__half2*)(Xs + r * KST + f * 4)     = __floats2half2_rn(xr[j].x, xr[j].y);
                *(__half2*)(Xs + r * KST + f * 4 + 2) = __floats2half2_rn(xr[j].z, xr[j].w);
            }
        }
        if (kc + 1 < NE / 64) asm volatile("cp.async.wait_group 1;\n");
        else                  asm volatile("cp.async.wait_group 0;\n");
        __syncthreads();   // Xs stores + W[kc] visible to all

        // ---- prefetch X(kc+1) into regs (overlaps mma) ----
        if (kc + 1 < NE / 64) {
#pragma unroll
            for (int j = 0; j < 3; j++) {
                int c = tid + j * 384;
                if (c < 1024) {
                    int r = c >> 4, f = c & 15;
                    xr[j] = X4[(size_t)(row0 + r) * (NE / 4) + (kc + 1) * 16 + f];
                }
            }
        }

        // ---- mma ----
        const uint32_t xb = smem_u32(Xs);
        const uint32_t wb = smem_u32(WBUF(buf, mi));
#pragma unroll
        for (int ks = 0; ks < 4; ks++) {
            uint32_t a[4];
            ldsm4(a[0], a[1], a[2], a[3],
                  xb + ((m0 + (mm & 1) * 8 + rr) * KST + ks * 16 + (mm >> 1) * 8) * 2);
#pragma unroll
            for (int j = 0; j < 4; j++) {
                uint32_t b0, b1, b2, b3;
                ldsm4t(b0, b1, b2, b3,
                       wb + ((ks * 16 + (mm & 1) * 8 + rr) * KST + j * 16 + (mm >> 1) * 8) * 2);
                mma16816(acc[2 * j], a, b0, b1);
                mma16816(acc[2 * j + 1], a, b2, b3);
            }
        }
        __syncthreads();   // all warps done with Xs and Wbuf[buf]

        // ---- refill freed W buffer for chunk kc+2 ----
        if (kc + 2 < NE / 64) load_w(kc + 2, buf);
    }

    __half* outp = (mi == 0) ? g_q : ((mi == 1) ? g_k : g_v);
    const float sc = (mi == 0) ? QSCALE : 1.0f;
    const int r0 = row0 + m0 + g, r1 = r0 + 8;
#pragma unroll
    for (int nt = 0; nt < 8; nt++) {
        int c = nt * 8 + 2 * tig;
        *(__half2*)(outp + (size_t)r0 * HS + c) =
            __floats2half2_rn(acc[nt][0] * sc, acc[nt][1] * sc);
        *(__half2*)(outp + (size_t)r1 * HS + c) =
            __floats2half2_rn(acc[nt][2] * sc, acc[nt][3] * sc);
    }
#undef WBUF
}

// ---------------------------------------------------------------------------
// Flash attention, split-K chunks of <=16 KV tiles.
// qb < 16 (nc==1): direct normalized output write.  Else: partials.
// ---------------------------------------------------------------------------
__global__ __launch_bounds__(128, 4) void attn_kernel(float* __restrict__ out) {
    const int qb = blockIdx.x;
    const int b = blockIdx.y;
    const int ci = blockIdx.z;

    const int kbEndFull = (qb < IL / 64) ? (IL / 64) : (qb + 1);
    const int c0 = ci * CHUNK;
    if (c0 >= kbEndFull) return;
    const int n = min(CHUNK, kbEndFull - c0);
    const int nc = (kbEndFull + CHUNK - 1) / CHUNK;

    const int tid = threadIdx.x, lane = tid & 31, warp = tid >> 5;
    const int g = lane >> 2, tig = lane & 3;
    const int mm = lane >> 3, rr = lane & 7;
    const int m0 = warp * 16;

    const __half* Q = g_q + (size_t)b * CL * HS + (size_t)qb * 64 * HS;
    const __half* K = g_k + (size_t)b * CL * HS + (size_t)c0 * 64 * HS;
    const __half* V = g_v + (size_t)b * CL * HS + (size_t)c0 * 64 * HS;

    __half* Ks[2] = {sm_dyn, sm_dyn + 2 * 64 * KST};
    __half* Vs[2] = {sm_dyn + 64 * KST, sm_dyn + 3 * 64 * KST};

    for (int i = tid; i < 512; i += 128) {
        int r = i >> 3, f = i & 7;
        *(uint4*)(Ks[0] + r * KST + f * 8) = *(const uint4*)(Q + r * HS + f * 8);
    }
    __syncthreads();
    uint32_t qa[4][4];
    {
        const uint32_t qbase = smem_u32(Ks[0]);
#pragma unroll
        for (int kc = 0; kc < 4; kc++)
            ldsm4(qa[kc][0], qa[kc][1], qa[kc][2], qa[kc][3],
                  qbase + ((m0 + (mm & 1) * 8 + rr) * KST + kc * 16 + (mm >> 1) * 8) * 2);
    }
    __syncthreads();

#pragma unroll
    for (int pf = 0; pf < 2; pf++) {
        const __half* gk = K + (size_t)pf * 64 * HS;
        const __half* gv = V + (size_t)pf * 64 * HS;
#pragma unroll
        for (int i = 0; i < 4; i++) {
            int c = tid + i * 128, r = c >> 3, f = c & 7;
            cp16(smem_u32(Ks[pf] + r * KST + f * 8), gk + r * HS + f * 8);
            cp16(smem_u32(Vs[pf] + r * KST + f * 8), gv + r * HS + f * 8);
        }
        asm volatile("cp.async.commit_group;\n");
    }

    float o[8][4] = {};
    float s[8][4] = {};
    float m[2] = {-1e30f, -1e30f};
    float l[2] = {0.f, 0.f};
    uint32_t pa[4][4];

    asm volatile("cp.async.wait_group 1;\n");
    __syncthreads();
    {
        const uint32_t kbase = smem_u32(Ks[0]);
#pragma unroll
        for (int kc = 0; kc < 4; kc++)
#pragma unroll
            for (int j = 0; j < 4; j++) {
                uint32_t b0, b1, b2, b3;
                ldsm4(b0, b1, b2, b3,
                      kbase + ((16 * j + (mm >> 1) * 8 + rr) * KST + kc * 16 + (mm & 1) * 8) * 2);
                mma16816(s[2 * j], qa[kc], b0, b1);
                mma16816(s[2 * j + 1], qa[kc], b2, b3);
            }
        if (c0 == qb && qb >= IL / 64) {
            const int r0 = m0 + g, r1 = r0 + 8;
#pragma unroll
            for (int nt = 0; nt < 8; nt++) {
                int c = nt * 8 + 2 * tig;
                if (c > r0)     s[nt][0] = -1e30f;
                if (c + 1 > r0) s[nt][1] = -1e30f;
                if (c > r1)     s[nt][2] = -1e30f;
                if (c + 1 > r1) s[nt][3] = -1e30f;
            }
        }
    }

    for (int i = 0; i < n; i++) {
        const int bi = i & 1;

#pragma unroll
        for (int h = 0; h < 2; h++) {
            float rm = -1e30f;
#pragma unroll
            for (int nt = 0; nt < 8; nt++)
                rm = fmaxf(rm, fmaxf(s[nt][2 * h], s[nt][2 * h + 1]));
            rm = fmaxf(rm, __shfl_xor_sync(0xffffffffu, rm, 1));
            rm = fmaxf(rm, __shfl_xor_sync(0xffffffffu, rm, 2));
            float mn = fmaxf(m[h], rm);
            float alpha = ex2f(m[h] - mn);
            m[h] = mn;
            float sum = 0.f;
#pragma unroll
            for (int nt = 0; nt < 8; nt++) {
                uint32_t p = h2exp2u(h2_as_u32(
                    __floats2half2_rn(s[nt][2 * h] - mn, s[nt][2 * h + 1] - mn)));
                pa[nt >> 1][(nt & 1) * 2 + h] = p;
                float2 f = __half22float2(*reinterpret_cast<__half2*>(&p));
                sum += f.x + f.y;
                o[nt][2 * h] *= alpha;
                o[nt][2 * h + 1] *= alpha;
            }
            sum += __shfl_xor_sync(0xffffffffu, sum, 1);
            sum += __shfl_xor_sync(0xffffffffu, sum, 2);
            l[h] = l[h] * alpha + sum;
        }

        if (i + 1 < n) {
            asm volatile("cp.async.wait_group 0;\n");
            __syncthreads();

#pragma unroll
            for (int nt = 0; nt < 8; nt++)
#pragma unroll
                for (int e = 0; e < 4; e++) s[nt][e] = 0.f;

            const uint32_t vbase = smem_u32(Vs[bi]);
            const uint32_t kbase = smem_u32(Ks[bi ^ 1]);
#pragma unroll
            for (int kc = 0; kc < 4; kc++)
#pragma unroll
                for (int j = 0; j < 4; j++) {
                    uint32_t v0, v1, v2, v3, k0, k1, k2, k3;
                    ldsm4t(v0, v1, v2, v3,
                           vbase + ((kc * 16 + (mm & 1) * 8 + rr) * KST + 16 * j + (mm >> 1) * 8) * 2);
                    ldsm4(k0, k1, k2, k3,
                          kbase + ((16 * j + (mm >> 1) * 8 + rr) * KST + kc * 16 + (mm & 1) * 8) * 2);
                    mma16816(o[2 * j], pa[kc], v0, v1);
                    mma16816(o[2 * j + 1], pa[kc], v2, v3);
                    mma16816(s[2 * j], qa[kc], k0, k1);
                    mma16816(s[2 * j + 1], qa[kc], k2, k3);
                }

            if (c0 + i + 1 == qb && qb >= IL / 64) {
                const int r0 = m0 + g, r1 = r0 + 8;
#pragma unroll
                for (int nt = 0; nt < 8; nt++) {
                    int c = nt * 8 + 2 * tig;
                    if (c > r0)     s[nt][0] = -1e30f;
                    if (c + 1 > r0) s[nt][1] = -1e30f;
                    if (c > r1)     s[nt][2] = -1e30f;
                    if (c + 1 > r1) s[nt][3] = -1e30f;
                }
            }
            __syncthreads();

            if (i + 2 < n) {
                const __half* gk = K + (size_t)(i + 2) * 64 * HS;
                const __half* gv = V + (size_t)(i + 2) * 64 * HS;
#pragma unroll
                for (int ii = 0; ii < 4; ii++) {
                    int c = tid + ii * 128, r = c >> 3, f = c & 7;
                    cp16(smem_u32(Ks[bi] + r * KST + f * 8), gk + r * HS + f * 8);
                    cp16(smem_u32(Vs[bi] + r * KST + f * 8), gv + r * HS + f * 8);
                }
                asm volatile("cp.async.commit_group;\n");
            }
        } else {
            const uint32_t vbase = smem_u32(Vs[bi]);
#pragma unroll
            for (int kc = 0; kc < 4; kc++)
#pragma unroll
                for (int j = 0; j < 4; j++) {
                    uint32_t v0, v1, v2, v3;
                    ldsm4t(v0, v1, v2, v3,
                           vbase + ((kc * 16 + (mm & 1) * 8 + rr) * KST + 16 * j + (mm >> 1) * 8) * 2);
                    mma16816(o[2 * j], pa[kc], v0, v1);
                    mma16816(o[2 * j + 1], pa[kc], v2, v3);
                }
        }
    }

    // ---- epilogue ----
    const int r0 = m0 + g, r1 = r0 + 8;
    if (nc == 1) {   // prefix blocks: final output directly
        float* O = out + ((size_t)b * CL + qb * 64) * HS;
        const float inv0 = 1.0f / l[0], inv1 = 1.0f / l[1];
#pragma unroll
        for (int nt = 0; nt < 8; nt++) {
            int c = nt * 8 + 2 * tig;
            O[(size_t)r0 * HS + c]     = o[nt][0] * inv0;
            O[(size_t)r0 * HS + c + 1] = o[nt][1] * inv0;
            O[(size_t)r1 * HS + c]     = o[nt][2] * inv1;
            O[(size_t)r1 * HS + c + 1] = o[nt][3] * inv1;
        }
        return;
    }

    const int slot = (b * 64 + qb) * 4 + ci;
    float* PO = g_part_o + (size_t)slot * 4096;
#pragma unroll
    for (int nt = 0; nt < 8; nt++) {
        int c = nt * 8 + 2 * tig;
        PO[r0 * 64 + c]     = o[nt][0];
        PO[r0 * 64 + c + 1] = o[nt][1];
        PO[r1 * 64 + c]     = o[nt][2];
        PO[r1 * 64 + c + 1] = o[nt][3];
    }
    if (tig == 0) {
        float* ML = g_part_ml + (size_t)slot * 128;
        ML[r0 * 2]     = m[0];
        ML[r0 * 2 + 1] = l[0];
        ML[r1 * 2]     = m[1];
        ML[r1 * 2 + 1] = l[1];
    }
}

// ---------------------------------------------------------------------------
// Combine split-K partials — causal blocks only (qb >= 16; nc in 2..4).
// ---------------------------------------------------------------------------
__global__ __launch_bounds__(256) void combine_kernel(float* __restrict__ out) {
    const int qb = 16 + blockIdx.x;            // 16..63
    const int b = blockIdx.y;
    const int nc = (qb + 16) / 16;             // ceil((qb+1)/16), qb>=16
    const int tid = threadIdx.x;
    const int slot0 = (b * 64 + qb) * 4;

    __shared__ float wsc[4][64];

    if (tid < 64) {
        float mv[4], lv[4];
        float M = -1e30f;
        for (int ci = 0; ci < nc; ci++) {
            mv[ci] = g_part_ml[(size_t)(slot0 + ci) * 128 + tid * 2];
            lv[ci] = g_part_ml[(size_t)(slot0 + ci) * 128 + tid * 2 + 1];
            M = fmaxf(M, mv[ci]);
        }
        float L = 0.f;
        for (int ci = 0; ci < nc; ci++) {
            float w = ex2f(mv[ci] - M);
            mv[ci] = w;
            L += lv[ci] * w;
        }
        float invL = 1.0f / L;
        for (int ci = 0; ci < nc; ci++) wsc[ci][tid] = mv[ci] * invL;
    }
    __syncthreads();

    const float4* P = (const float4*)(g_part_o + (size_t)slot0 * 4096);
    float4* O = (float4*)(out + ((size_t)b * CL + qb * 64) * HS);
#pragma unroll
    for (int k = 0; k < 4; k++) {
        int idx = tid + k * 256;   // 0..1023 float4 (64 rows x 16)
        int row = idx >> 4;
        float4 acc = {0.f, 0.f, 0.f, 0.f};
        for (int ci = 0; ci < nc; ci++) {
            float w = wsc[ci][row];
            float4 v = P[ci * 1024 + idx];
            acc.x += v.x * w;
            acc.y += v.y * w;
            acc.z += v.z * w;
            acc.w += v.w * w;
        }
        O[idx] = acc;
    }
}

extern "C" void kernel_launch(void* const* d_in, const int* in_sizes, int n_in,
                              void* d_out, int out_size) {
    const float* x  = (const float*)d_in[0];
    const float* Wq = (const float*)d_in[1];
    const float* Wk = (const float*)d_in[2];
    const float* Wv = (const float*)d_in[3];
    float* out = (float*)d_out;

    convw_kernel<<<96, 256>>>(Wq, Wk, Wv);

    const int proj_smem = (64 + 6 * 64) * KST * (int)sizeof(__half);  // 64512
    cudaFuncSetAttribute(proj_kernel, cudaFuncAttributeMaxDynamicSharedMemorySize,
                         proj_smem);
    proj_kernel<<<BATCHN * CL / 64, 384, proj_smem>>>(x);

    const int attn_smem = 4 * 64 * KST * (int)sizeof(__half);  // 36864
    dim3 gattn(CL / 64, BATCHN, 4);
    attn_kernel<<<gattn, 128, attn_smem>>>(out);

    dim3 gcomb(48, BATCHN);
    combine_kernel<<<gcomb, 256>>>(out);
}